// round 12
// baseline (speedup 1.0000x reference)
#include <cuda_runtime.h>
#include <math.h>

// Problem constants
#define BATCH 64
#define NSEP  6
#define SLEN  256
#define TLEN  64
#define DMODEL 512
#define NHEAD 4
#define DHEAD 128
#define FFDIM 512
#define NLAYER 4
#define IMGDIM 2048

#define MAIN_TOK (BATCH*SLEN)          // 16384
#define HIST_SEQ (BATCH*NSEP)          // 384
#define HIST_TOK (HIST_SEQ*TLEN)       // 24576
#define MAXTOK   HIST_TOK

// ---------------- scratch (device globals; no allocation allowed) ------------
__device__ float g_x [MAXTOK*DMODEL];
__device__ float g_q [MAXTOK*DMODEL];
__device__ float g_k [MAXTOK*DMODEL];
__device__ float g_v [MAXTOK*DMODEL];
__device__ float g_t1[MAXTOK*DMODEL];
__device__ float g_t2[MAXTOK*DMODEL];
__device__ float g_hidden[BATCH*DMODEL];
__device__ float g_sep[HIST_SEQ*DMODEL];

// Pre-rounded (tf32/rna) weights: 0:Wq 1:Wk 2:Wv 3:Wo 4:W1 5:W2 6:Wsep
#define WTSZ 1048576
__device__ float g_wr[7*WTSZ];

__device__ __forceinline__ float tf32r(float x)
{
    unsigned u;
    asm("cvt.rna.tf32.f32 %0, %1;" : "=r"(u) : "f"(x));
    return __uint_as_float(u);
}

// ---------------- one-time weight rounding (single launch, grid.y = tensor) --
__global__ void wround_all(const float* w0, const float* w1, const float* w2,
                           const float* w3, const float* w4, const float* w5,
                           const float* w6, float* out, int n4)
{
    const float* srcs[7] = { w0, w1, w2, w3, w4, w5, w6 };
    int t = blockIdx.y;
    const float* w = srcs[t];
    float* o = out + (size_t)t * WTSZ;
    int i = blockIdx.x * 256 + threadIdx.x;
    if (i >= n4) return;
    float4 v = ((const float4*)w)[i];
    v.x = tf32r(v.x); v.y = tf32r(v.y); v.z = tf32r(v.z); v.w = tf32r(v.w);
    ((float4*)o)[i] = v;
}

// =====================================================================
// tf32 tensor-core GEMM: C = A[M,K] @ W[K,N] + bias, optional ReLU.
// W pre-rounded; A raw (HW truncates fp32->tf32 in the mma).
// Block 128x128x32, 256 threads (8 warps 4x2), warp tile 32x64.
// k-PERMUTED smem layout: within each 8-k block, position
//   p(k) = ((k&3)<<1) | ((k>>2)&1)
// so a fragment's (k, k+4) pair is adjacent -> LDS.64 fragment loads.
// Register-prefetch staging, single buffer, 2 barriers per 32-k tile.
// Requires: M%128==0, N%128==0, K%32==0 (all call sites satisfy).
// =====================================================================
#define TBM 128
#define TBN 128
#define TBK 32
#define SSTR 36    // float stride per row: 32 data + 4 pad

__device__ __forceinline__ void mma1688(float* d, const unsigned* a, const unsigned* b)
{
    asm volatile(
        "mma.sync.aligned.m16n8k8.row.col.f32.tf32.tf32.f32 "
        "{%0,%1,%2,%3},{%4,%5,%6,%7},{%8,%9},{%0,%1,%2,%3};"
        : "+f"(d[0]), "+f"(d[1]), "+f"(d[2]), "+f"(d[3])
        : "r"(a[0]), "r"(a[1]), "r"(a[2]), "r"(a[3]), "r"(b[0]), "r"(b[1]));
}

__global__ __launch_bounds__(256) void gemm_tf32(
    const float* __restrict__ A, const float* __restrict__ W,
    const float* __restrict__ bias, float* __restrict__ C,
    int M, int N, int K, int relu)
{
    __shared__ float As[TBM * SSTR];   // [row][pk]
    __shared__ float Bs[TBN * SSTR];   // [n][pk]

    int tid  = threadIdx.x;
    int warp = tid >> 5, lane = tid & 31;
    int wm = warp & 3, wn = warp >> 2;         // 4 x 2 warps
    int g = lane >> 2, c = lane & 3;

    int brow = blockIdx.y * TBM;
    int bcol = blockIdx.x * TBN;

    float acc[2][8][4];
    #pragma unroll
    for (int mt = 0; mt < 2; mt++)
        #pragma unroll
        for (int nt = 0; nt < 8; nt++)
            #pragma unroll
            for (int i = 0; i < 4; i++) acc[mt][nt][i] = 0.f;

    // A staging: row = tid>>1, k-offset (tid&1)*16, 4 float4 per tile
    int a_row = tid >> 1, a_ko = (tid & 1) << 4;
    const float* aptr = A + (size_t)(brow + a_row) * K + a_ko;
    // B staging: k-row bk = tid&31, 16 n-cols at (tid>>5)*16
    int bk = tid & 31, bn0 = (tid >> 5) << 4;
    const float* bptr = W + (size_t)bk * N + bcol + bn0;
    int pkb = (bk & ~7) + ((bk & 3) << 1) + ((bk >> 2) & 1);

    int niter = K / TBK;

    // prologue: fetch tile 0
    float4 ar0 = *(const float4*)(aptr + 0);
    float4 ar1 = *(const float4*)(aptr + 4);
    float4 ar2 = *(const float4*)(aptr + 8);
    float4 ar3 = *(const float4*)(aptr + 12);
    float4 br0 = *(const float4*)(bptr + 0);
    float4 br1 = *(const float4*)(bptr + 4);
    float4 br2 = *(const float4*)(bptr + 8);
    float4 br3 = *(const float4*)(bptr + 12);

    for (int i = 0; i < niter; i++) {
        // ---- stage A (permuted pairs: pos 2j holds k=j, pos 2j+1 holds k=j+4) ----
        {
            float* arow = As + a_row * SSTR + a_ko;
            *(float2*)(arow + 0)  = make_float2(ar0.x, ar1.x);
            *(float2*)(arow + 2)  = make_float2(ar0.y, ar1.y);
            *(float2*)(arow + 4)  = make_float2(ar0.z, ar1.z);
            *(float2*)(arow + 6)  = make_float2(ar0.w, ar1.w);
            *(float2*)(arow + 8)  = make_float2(ar2.x, ar3.x);
            *(float2*)(arow + 10) = make_float2(ar2.y, ar3.y);
            *(float2*)(arow + 12) = make_float2(ar2.z, ar3.z);
            *(float2*)(arow + 14) = make_float2(ar2.w, ar3.w);
        }
        // ---- stage B (transpose, permuted k position; conflict-free) ----
        {
            Bs[(bn0 + 0)*SSTR + pkb]  = br0.x;  Bs[(bn0 + 1)*SSTR + pkb]  = br0.y;
            Bs[(bn0 + 2)*SSTR + pkb]  = br0.z;  Bs[(bn0 + 3)*SSTR + pkb]  = br0.w;
            Bs[(bn0 + 4)*SSTR + pkb]  = br1.x;  Bs[(bn0 + 5)*SSTR + pkb]  = br1.y;
            Bs[(bn0 + 6)*SSTR + pkb]  = br1.z;  Bs[(bn0 + 7)*SSTR + pkb]  = br1.w;
            Bs[(bn0 + 8)*SSTR + pkb]  = br2.x;  Bs[(bn0 + 9)*SSTR + pkb]  = br2.y;
            Bs[(bn0 +10)*SSTR + pkb]  = br2.z;  Bs[(bn0 +11)*SSTR + pkb]  = br2.w;
            Bs[(bn0 +12)*SSTR + pkb]  = br3.x;  Bs[(bn0 +13)*SSTR + pkb]  = br3.y;
            Bs[(bn0 +14)*SSTR + pkb]  = br3.z;  Bs[(bn0 +15)*SSTR + pkb]  = br3.w;
        }
        __syncthreads();

        // ---- prefetch next tile (hidden by the long mma chain) ----
        if (i + 1 < niter) {
            const float* ga = aptr + (size_t)(i + 1) * TBK;
            ar0 = *(const float4*)(ga + 0);
            ar1 = *(const float4*)(ga + 4);
            ar2 = *(const float4*)(ga + 8);
            ar3 = *(const float4*)(ga + 12);
            const float* gb = bptr + (size_t)(i + 1) * TBK * N;
            br0 = *(const float4*)(gb + 0);
            br1 = *(const float4*)(gb + 4);
            br2 = *(const float4*)(gb + 8);
            br3 = *(const float4*)(gb + 12);
        }

        // ---- compute: 4 k-steps of 8 ----
        #pragma unroll
        for (int ks = 0; ks < 4; ks++) {
            int kp = ks * 8 + 2 * c;          // permuted pair position
            float2 bf2[8];
            #pragma unroll
            for (int nt = 0; nt < 8; nt++) {
                int n = wn * 64 + nt * 8 + g;
                bf2[nt] = *(const float2*)&Bs[n * SSTR + kp];
            }
            #pragma unroll
            for (int mt = 0; mt < 2; mt++) {
                int r0 = wm * 32 + mt * 16 + g;
                float2 aLo = *(const float2*)&As[r0 * SSTR + kp];
                float2 aHi = *(const float2*)&As[(r0 + 8) * SSTR + kp];
                unsigned af[4];
                af[0] = __float_as_uint(aLo.x);   // (row g,   k)
                af[1] = __float_as_uint(aHi.x);   // (row g+8, k)
                af[2] = __float_as_uint(aLo.y);   // (row g,   k+4)
                af[3] = __float_as_uint(aHi.y);   // (row g+8, k+4)
                #pragma unroll
                for (int nt = 0; nt < 8; nt++) {
                    unsigned bf[2] = { __float_as_uint(bf2[nt].x),
                                       __float_as_uint(bf2[nt].y) };
                    mma1688(acc[mt][nt], af, bf);
                }
            }
        }
        __syncthreads();
    }

    // ---- epilogue: bias (+relu) + store ----
    #pragma unroll
    for (int mt = 0; mt < 2; mt++) {
        int row = brow + wm * 32 + mt * 16 + g;
        #pragma unroll
        for (int nt = 0; nt < 8; nt++) {
            int col = bcol + wn * 64 + nt * 8 + 2 * c;
            float2 bs = *(const float2*)(bias + col);
            float v0 = acc[mt][nt][0] + bs.x;
            float v1 = acc[mt][nt][1] + bs.y;
            float v2 = acc[mt][nt][2] + bs.x;
            float v3 = acc[mt][nt][3] + bs.y;
            if (relu) {
                v0 = fmaxf(v0, 0.f); v1 = fmaxf(v1, 0.f);
                v2 = fmaxf(v2, 0.f); v3 = fmaxf(v3, 0.f);
            }
            *(float2*)(C + (size_t)row * N + col)       = make_float2(v0, v1);
            *(float2*)(C + (size_t)(row + 8) * N + col) = make_float2(v2, v3);
        }
    }
}

// =====================================================================
// Attention: block per (seq m, head h, 64-row q-tile), 256 threads.
// =====================================================================
#define QT 64
#define KC 64
#define QSTR 129
#define KSTR 129
#define VSTR 132

__global__ __launch_bounds__(256) void attn2_kernel(
    const float* __restrict__ q, const float* __restrict__ k,
    const float* __restrict__ v, float* __restrict__ out,
    const int* __restrict__ lens, int Tt, int nQT)
{
    extern __shared__ float sm[];
    float* Qs  = sm;
    float* KVs = Qs + QT * QSTR;
    float* SC  = KVs + KC * VSTR;

    int tid = threadIdx.x;
    int b = blockIdx.x;
    int qt  = b % nQT; int rem = b / nQT;
    int h = rem % NHEAD; int m = rem / NHEAD;
    int q0 = qt * QT;
    int sstr = Tt + 1;

    int valid = Tt;
    if (lens) { int l = lens[m]; valid = l > 1 ? l : 1; }

    // ---- load Q tile ----
    const float* qbase = q + ((size_t)m * Tt + q0) * DMODEL + h * DHEAD;
    for (int i = tid; i < QT * (DHEAD/4); i += 256) {
        int row = i >> 5, c4 = i & 31;
        float4 vq = *(const float4*)(qbase + (size_t)row * DMODEL + 4 * c4);
        float* dst = Qs + row * QSTR + 4 * c4;
        dst[0] = vq.x; dst[1] = vq.y; dst[2] = vq.z; dst[3] = vq.w;
    }

    // ---- phase 1: raw scores ----
    int tq = (tid >> 4) << 2;
    int tk = (tid & 15) << 2;
    for (int kc = 0; kc < Tt; kc += KC) {
        __syncthreads();
        const float* kbase = k + ((size_t)m * Tt + kc) * DMODEL + h * DHEAD;
        for (int i = tid; i < KC * (DHEAD/4); i += 256) {
            int row = i >> 5, c4 = i & 31;
            float4 vk = *(const float4*)(kbase + (size_t)row * DMODEL + 4 * c4);
            float* dst = KVs + row * KSTR + 4 * c4;
            dst[0] = vk.x; dst[1] = vk.y; dst[2] = vk.z; dst[3] = vk.w;
        }
        __syncthreads();

        float acc[4][4];
        #pragma unroll
        for (int i = 0; i < 4; i++)
            #pragma unroll
            for (int j = 0; j < 4; j++) acc[i][j] = 0.f;

        const float* qp0 = Qs + (tq + 0) * QSTR;
        const float* qp1 = Qs + (tq + 1) * QSTR;
        const float* qp2 = Qs + (tq + 2) * QSTR;
        const float* qp3 = Qs + (tq + 3) * QSTR;
        const float* kp0 = KVs + (tk + 0) * KSTR;
        const float* kp1 = KVs + (tk + 1) * KSTR;
        const float* kp2 = KVs + (tk + 2) * KSTR;
        const float* kp3 = KVs + (tk + 3) * KSTR;

        #pragma unroll 4
        for (int d = 0; d < DHEAD; d++) {
            float qa[4] = { qp0[d], qp1[d], qp2[d], qp3[d] };
            float kb[4] = { kp0[d], kp1[d], kp2[d], kp3[d] };
            #pragma unroll
            for (int i = 0; i < 4; i++)
                #pragma unroll
                for (int j = 0; j < 4; j++)
                    acc[i][j] += qa[i] * kb[j];
        }
        #pragma unroll
        for (int i = 0; i < 4; i++)
            #pragma unroll
            for (int j = 0; j < 4; j++)
                SC[(tq + i) * sstr + kc + tk + j] = acc[i][j];
    }
    __syncthreads();

    // ---- phase 2: softmax per row ----
    {
        int warp = tid >> 5, lane = tid & 31;
        const float scale = 0.08838834764831845f;   // 1/sqrt(128)
        for (int rr = 0; rr < 8; rr++) {
            float* row = SC + (warp * 8 + rr) * sstr;
            float mx = -1e30f;
            for (int j = lane; j < Tt; j += 32) {
                float s = (j < valid) ? row[j] * scale : -1e9f;
                row[j] = s;
                mx = fmaxf(mx, s);
            }
            #pragma unroll
            for (int o = 16; o; o >>= 1) mx = fmaxf(mx, __shfl_xor_sync(0xffffffffu, mx, o));
            float sum = 0.f;
            for (int j = lane; j < Tt; j += 32) {
                float e = __expf(row[j] - mx);
                row[j] = e;
                sum += e;
            }
            #pragma unroll
            for (int o = 16; o; o >>= 1) sum += __shfl_xor_sync(0xffffffffu, sum, o);
            float inv = 1.f / sum;
            for (int j = lane; j < Tt; j += 32) row[j] *= inv;
        }
    }

    // ---- phase 3: P @ V ----
    int tqg = (tid >> 4) << 2;
    int td  = (tid & 15) << 3;
    float cacc[4][8];
    #pragma unroll
    for (int i = 0; i < 4; i++)
        #pragma unroll
        for (int j = 0; j < 8; j++) cacc[i][j] = 0.f;

    for (int kc = 0; kc < Tt; kc += KC) {
        __syncthreads();
        const float* vbase = v + ((size_t)m * Tt + kc) * DMODEL + h * DHEAD;
        for (int i = tid; i < KC * (DHEAD/4); i += 256) {
            int row = i >> 5, c4 = i & 31;
            float4 vv = *(const float4*)(vbase + (size_t)row * DMODEL + 4 * c4);
            *(float4*)(KVs + row * VSTR + 4 * c4) = vv;
        }
        __syncthreads();

        const float* pp0 = SC + (tqg + 0) * sstr + kc;
        const float* pp1 = SC + (tqg + 1) * sstr + kc;
        const float* pp2 = SC + (tqg + 2) * sstr + kc;
        const float* pp3 = SC + (tqg + 3) * sstr + kc;
        #pragma unroll 2
        for (int kk = 0; kk < KC; kk++) {
            float p[4] = { pp0[kk], pp1[kk], pp2[kk], pp3[kk] };
            float4 v0 = *(const float4*)(KVs + kk * VSTR + td);
            float4 v1 = *(const float4*)(KVs + kk * VSTR + td + 4);
            float vv[8] = { v0.x, v0.y, v0.z, v0.w, v1.x, v1.y, v1.z, v1.w };
            #pragma unroll
            for (int i = 0; i < 4; i++)
                #pragma unroll
                for (int j = 0; j < 8; j++)
                    cacc[i][j] += p[i] * vv[j];
        }
    }

    // ---- store ctx ----
    float* obase = out + ((size_t)m * Tt + q0) * DMODEL + h * DHEAD;
    #pragma unroll
    for (int i = 0; i < 4; i++) {
        float* orow = obase + (size_t)(tqg + i) * DMODEL + td;
        *(float4*)(orow)     = make_float4(cacc[i][0], cacc[i][1], cacc[i][2], cacc[i][3]);
        *(float4*)(orow + 4) = make_float4(cacc[i][4], cacc[i][5], cacc[i][6], cacc[i][7]);
    }
}

// ---------------- residual add + LayerNorm, block per token -----------------
__global__ void add_ln_kernel(const float* __restrict__ x, const float* __restrict__ y,
                              const float* __restrict__ g, const float* __restrict__ b,
                              float* __restrict__ out)
{
    int t = blockIdx.x, tid = threadIdx.x;
    const float* xr = x + (size_t)t * DMODEL;
    const float* yr = y + (size_t)t * DMODEL;
    int lane = tid & 31, warp = tid >> 5;
    __shared__ float red[4];

    float h[4];
    float s = 0.f;
    #pragma unroll
    for (int i = 0; i < 4; i++) { int d = tid + i * 128; h[i] = xr[d] + yr[d]; s += h[i]; }
    #pragma unroll
    for (int o = 16; o; o >>= 1) s += __shfl_xor_sync(0xffffffffu, s, o);
    if (lane == 0) red[warp] = s;
    __syncthreads();
    s = red[0] + red[1] + red[2] + red[3];
    float mu = s * (1.f / DMODEL);

    float vs = 0.f;
    #pragma unroll
    for (int i = 0; i < 4; i++) { float dl = h[i] - mu; vs += dl * dl; }
    #pragma unroll
    for (int o = 16; o; o >>= 1) vs += __shfl_xor_sync(0xffffffffu, vs, o);
    __syncthreads();
    if (lane == 0) red[warp] = vs;
    __syncthreads();
    vs = (red[0] + red[1] + red[2] + red[3]) * (1.f / DMODEL);
    float invstd = rsqrtf(vs + 1e-5f);

    float* orow = out + (size_t)t * DMODEL;
    #pragma unroll
    for (int i = 0; i < 4; i++) {
        int d = tid + i * 128;
        orow[d] = (h[i] - mu) * invstd * g[d] + b[d];
    }
}

// ---------------- embedding + positional encoding ---------------------------
__device__ __forceinline__ float pe_val(int pos, int d)
{
    int i2 = d & ~1;
    float div = expf((float)i2 * (-9.210340371976184f / (float)DMODEL));
    float ang = (float)pos * div;
    return (d & 1) ? cosf(ang) : sinf(ang);
}

__global__ void embed_kernel(const int* __restrict__ ids, const float* __restrict__ emb,
                             float* __restrict__ x, int seqlen)
{
    int tok = blockIdx.x;
    int pos = tok % seqlen;
    int id = ids[tok];
    const float* erow = emb + (size_t)id * DMODEL;
    float* xrow = x + (size_t)tok * DMODEL;
    for (int d = threadIdx.x; d < DMODEL; d += 128)
        xrow[d] = erow[d] + pe_val(pos, d);
}

// ---------------- small epilogue kernels -------------------------------------
__global__ void copy_hidden_kernel(const float* __restrict__ x, float* __restrict__ hid)
{
    int b = blockIdx.x;
    const float* src = x + ((size_t)(b * SLEN + SLEN - 1)) * DMODEL;
    for (int d = threadIdx.x; d < DMODEL; d += 128)
        hid[b * DMODEL + d] = src[d];
}

__global__ void gather_add_kernel(const float* __restrict__ hx, const int* __restrict__ lens,
                                  float* __restrict__ sep)
{
    int r = blockIdx.x;
    int len = lens[r];
    if (len <= 0) return;
    const float* src = hx + ((size_t)(r * TLEN + len - 1)) * DMODEL;
    for (int d = threadIdx.x; d < DMODEL; d += 128)
        sep[(size_t)r * DMODEL + d] += src[d];
}

__global__ void final_kernel(const float* __restrict__ sep, const float* __restrict__ hidden,
                             const int* __restrict__ normalize, float* __restrict__ out)
{
    int r = blockIdx.x;
    int b = r / NSEP;
    int tid = threadIdx.x;
    int lane = tid & 31, warp = tid >> 5;
    int norm = *normalize;

    __shared__ float sbuf[DMODEL];
    __shared__ float red[4];

    for (int d = tid; d < DMODEL; d += 128) {
        float v = sep[(size_t)r * DMODEL + d];
        if (norm) v = fmaxf(v, 0.f);
        sbuf[d] = v;
    }
    __syncthreads();

    float scale = 1.f;
    if (norm) {
        float ss = 0.f;
        for (int d = tid; d < DMODEL; d += 128) ss += sbuf[d] * sbuf[d];
        #pragma unroll
        for (int o = 16; o; o >>= 1) ss += __shfl_xor_sync(0xffffffffu, ss, o);
        if (lane == 0) red[warp] = ss;
        __syncthreads();
        ss = red[0] + red[1] + red[2] + red[3];
        float nrm = sqrtf(ss);
        scale = 1.f / fmaxf(nrm, 1e-12f);
        __syncthreads();
    }

    float dp = 0.f;
    for (int d = tid; d < DMODEL; d += 128)
        dp += sbuf[d] * scale * hidden[(size_t)b * DMODEL + d];
    #pragma unroll
    for (int o = 16; o; o >>= 1) dp += __shfl_xor_sync(0xffffffffu, dp, o);
    if (lane == 0) red[warp] = dp;
    __syncthreads();
    if (tid == 0) out[r] = red[0] + red[1] + red[2] + red[3];
}

// ---------------- host side ---------------------------------------------------
static void gemm(const float* A, const float* Wr, const float* bias, float* C,
                 int M, int N, int K, int relu)
{
    dim3 grid(N / TBN, M / TBM);
    gemm_tf32<<<grid, 256>>>(A, Wr, bias, C, M, N, K, relu);
}

struct EncParams {
    const float *wr;
    const float *bq, *bk, *bv, *bo;
    const float *ln1g, *ln1b, *b1, *b2, *ln2g, *ln2b;
};

static void launch_attn(const float* q, const float* k, const float* v, float* out,
                        const int* lens, int M, int Tt)
{
    int nQT = Tt / QT;
    int grid = M * NHEAD * nQT;
    size_t smem = (size_t)(QT * QSTR + KC * VSTR + QT * (Tt + 1)) * sizeof(float);
    attn2_kernel<<<grid, 256, smem>>>(q, k, v, out, lens, Tt, nQT);
}

static void run_encoder(float* x, float* q, float* k, float* v, float* t1, float* t2,
                        const EncParams& p, const int* lens, int M, int Tt)
{
    int ntok = M * Tt;
    const int LW = DMODEL * DMODEL;
    for (int l = 0; l < NLAYER; l++) {
        const float* wq = p.wr + 0*WTSZ + (size_t)l * LW;
        const float* wk = p.wr + 1*WTSZ + (size_t)l * LW;
        const float* wv = p.wr + 2*WTSZ + (size_t)l * LW;
        const float* wo = p.wr + 3*WTSZ + (size_t)l * LW;
        const float* w1 = p.wr + 4*WTSZ + (size_t)l * LW;
        const float* w2 = p.wr + 5*WTSZ + (size_t)l * LW;

        gemm(x, wq, p.bq + l * DMODEL, q, ntok, DMODEL, DMODEL, 0);
        gemm(x, wk, p.bk + l * DMODEL, k, ntok, DMODEL, DMODEL, 0);
        gemm(x, wv, p.bv + l * DMODEL, v, ntok, DMODEL, DMODEL, 0);

        launch_attn(q, k, v, t1, lens, M, Tt);

        gemm(t1, wo, p.bo + l * DMODEL, t2, ntok, DMODEL, DMODEL, 0);
        add_ln_kernel<<<ntok, 128>>>(x, t2, p.ln1g + l * DMODEL, p.ln1b + l * DMODEL, x);

        gemm(x, w1, p.b1 + l * FFDIM, t1, ntok, FFDIM, DMODEL, 1);
        gemm(t1, w2, p.b2 + l * DMODEL, t2, ntok, DMODEL, FFDIM, 0);
        add_ln_kernel<<<ntok, 128>>>(x, t2, p.ln2g + l * DMODEL, p.ln2b + l * DMODEL, x);
    }
}

extern "C" void kernel_launch(void* const* d_in, const int* in_sizes, int n_in,
                              void* d_out, int out_size)
{
    const int*   segment    = (const int*)  d_in[0];
    const int*   prev_hist  = (const int*)  d_in[1];
    const int*   hist_len   = (const int*)  d_in[2];
    const float* sep_img    = (const float*)d_in[3];
    const int*   normalize  = (const int*)  d_in[4];
    const float* embedding  = (const float*)d_in[5];

    const float* Wq   = (const float*)d_in[6];  const float* bq   = (const float*)d_in[7];
    const float* Wk   = (const float*)d_in[8];  const float* bk   = (const float*)d_in[9];
    const float* Wv   = (const float*)d_in[10]; const float* bv   = (const float*)d_in[11];
    const float* Wo   = (const float*)d_in[12]; const float* bo   = (const float*)d_in[13];
    const float* ln1g = (const float*)d_in[14]; const float* ln1b = (const float*)d_in[15];
    const float* W1   = (const float*)d_in[16]; const float* b1   = (const float*)d_in[17];
    const float* W2   = (const float*)d_in[18]; const float* b2   = (const float*)d_in[19];
    const float* ln2g = (const float*)d_in[20]; const float* ln2b = (const float*)d_in[21];
    const float* Wsep = (const float*)d_in[22];
    const float* bsep = (const float*)d_in[23];

    float *x, *q, *k, *v, *t1, *t2, *hid, *sep, *wr;
    cudaGetSymbolAddress((void**)&x,   g_x);
    cudaGetSymbolAddress((void**)&q,   g_q);
    cudaGetSymbolAddress((void**)&k,   g_k);
    cudaGetSymbolAddress((void**)&v,   g_v);
    cudaGetSymbolAddress((void**)&t1,  g_t1);
    cudaGetSymbolAddress((void**)&t2,  g_t2);
    cudaGetSymbolAddress((void**)&hid, g_hidden);
    cudaGetSymbolAddress((void**)&sep, g_sep);
    cudaGetSymbolAddress((void**)&wr,  g_wr);

    cudaFuncSetAttribute(attn2_kernel, cudaFuncAttributeMaxDynamicSharedMemorySize, 140 * 1024);

    // ---- launch 1: round all weights to tf32 (single launch) ----
    {
        dim3 grid(WTSZ / 4 / 256, 7);
        wround_all<<<grid, 256>>>(Wq, Wk, Wv, Wo, W1, W2, Wsep, wr, WTSZ / 4);
    }

    EncParams p;
    p.wr = wr;
    p.bq = bq; p.bk = bk; p.bv = bv; p.bo = bo;
    p.ln1g = ln1g; p.ln1b = ln1b; p.b1 = b1; p.b2 = b2; p.ln2g = ln2g; p.ln2b = ln2b;

    // ---- launch 2: main embed; launch 3: image projection (independent) ----
    embed_kernel<<<MAIN_TOK, 128>>>(segment, embedding, x, SLEN);
    gemm(sep_img, wr + (size_t)6 * WTSZ, bsep, sep, HIST_SEQ, FFDIM, IMGDIM, 0);
    // launches 4,5,6: Wq, Wk, Wv GEMMs of layer 0 (ncu -s 5 captures #6)

    // ---- main encoder ----
    run_encoder(x, q, k, v, t1, t2, p, nullptr, BATCH, SLEN);
    copy_hidden_kernel<<<BATCH, 128>>>(x, hid);

    // ---- history encoder ----
    embed_kernel<<<HIST_TOK, 128>>>(prev_hist, embedding, x, TLEN);
    run_encoder(x, q, k, v, t1, t2, p, hist_len, HIST_SEQ, TLEN);

    // ---- gather last hidden, add to sep, normalize + dot ----
    gather_add_kernel<<<HIST_SEQ, 128>>>(x, hist_len, sep);
    final_kernel<<<HIST_SEQ, 128>>>(sep, hid, normalize, (float*)d_out);
}

// round 13
// speedup vs baseline: 1.4012x; 1.4012x over previous
#include <cuda_runtime.h>
#include <math.h>

// Problem constants
#define BATCH 64
#define NSEP  6
#define SLEN  256
#define TLEN  64
#define DMODEL 512
#define NHEAD 4
#define DHEAD 128
#define FFDIM 512
#define NLAYER 4
#define IMGDIM 2048
#define QKVN  1536     // fused q|k|v output width

#define MAIN_TOK (BATCH*SLEN)          // 16384
#define HIST_SEQ (BATCH*NSEP)          // 384
#define HIST_TOK (HIST_SEQ*TLEN)       // 24576
#define MAXTOK   HIST_TOK

// ---------------- scratch (device globals; no allocation allowed) ------------
__device__ float g_x  [MAXTOK*DMODEL];
__device__ float g_qkv[MAXTOK*QKVN];
__device__ float g_t1 [MAXTOK*DMODEL];
__device__ float g_t2 [MAXTOK*DMODEL];
__device__ float g_hidden[BATCH*DMODEL];
__device__ float g_sep[HIST_SEQ*DMODEL];

// Pre-rounded (tf32/rna) weights:
//   [0, 3145728)               wqkv: [L][512][1536]  (Wq|Wk|Wv per k-row)
//   +0: Wo  +1M: W1  +2M: W2  +3M: Wsep   (each [L?][512][512] / [2048][512])
#define WQKV_SZ (NLAYER*DMODEL*QKVN)          // 3,145,728
#define WTSZ    1048576
#define WR_TOTAL (WQKV_SZ + 4*WTSZ)
__device__ float g_wr[WR_TOTAL];
__device__ float g_bqkv[NLAYER*QKVN];

__device__ __forceinline__ float tf32r(float x)
{
    unsigned u;
    asm("cvt.rna.tf32.f32 %0, %1;" : "=r"(u) : "f"(x));
    return __uint_as_float(u);
}

// ---------------- weight pack+round kernels ----------------------------------
// launch 1: pack Wq|Wk|Wv -> wqkv [L][512][1536], rounded. float4 over n.
__global__ void pack_qkv(const float* __restrict__ Wq, const float* __restrict__ Wk,
                         const float* __restrict__ Wv, float* __restrict__ out)
{
    int i4 = blockIdx.x * 256 + threadIdx.x;          // float4 index
    int total4 = WQKV_SZ / 4;
    if (i4 >= total4) return;
    int idx = i4 * 4;
    int n = idx % QKVN;
    int lk = idx / QKVN;                              // l*512 + k
    const float* src;
    int c = n;
    if (n < 512)       { src = Wq; }
    else if (n < 1024) { src = Wk; c = n - 512; }
    else               { src = Wv; c = n - 1024; }
    float4 v = *(const float4*)(src + (size_t)lk * DMODEL + c);
    v.x = tf32r(v.x); v.y = tf32r(v.y); v.z = tf32r(v.z); v.w = tf32r(v.w);
    *(float4*)(out + idx) = v;
}

// launch 2: round Wo/W1/W2/Wsep (grid.y selects tensor)
__global__ void wround4(const float* w0, const float* w1, const float* w2,
                        const float* w3, float* out, int n4)
{
    const float* srcs[4] = { w0, w1, w2, w3 };
    int t = blockIdx.y;
    const float* w = srcs[t];
    float* o = out + WQKV_SZ + (size_t)t * WTSZ;
    int i = blockIdx.x * 256 + threadIdx.x;
    if (i >= n4) return;
    float4 v = ((const float4*)w)[i];
    v.x = tf32r(v.x); v.y = tf32r(v.y); v.z = tf32r(v.z); v.w = tf32r(v.w);
    ((float4*)o)[i] = v;
}

// launch 3: pack biases bq|bk|bv -> bqkv [L][1536]
__global__ void pack_bias(const float* __restrict__ bq, const float* __restrict__ bk,
                          const float* __restrict__ bv, float* __restrict__ out)
{
    int idx = blockIdx.x * 256 + threadIdx.x;
    if (idx >= NLAYER * QKVN) return;
    int n = idx % QKVN, l = idx / QKVN;
    float v;
    if (n < 512)       v = bq[l * DMODEL + n];
    else if (n < 1024) v = bk[l * DMODEL + n - 512];
    else               v = bv[l * DMODEL + n - 1024];
    out[idx] = v;
}

// =====================================================================
// tf32 tensor-core GEMM: C = A[M,K] @ W[K,N] + bias, optional ReLU.
// W pre-rounded; A raw (HW truncates fp32->tf32 in the mma).
// Block 128x128x16, 256 threads (8 warps 4x2), warp tile 32x64.
// 3-stage cp.async pipeline for BOTH A and B (no staging registers),
// ONE barrier per k-tile. B in natural [k][n] smem layout, BSTR=136
// (conflict-free fragment loads); A [row][k] ASTR=20.
// Requires: M%128==0, N%128==0, K%16==0 (all call sites satisfy).
// =====================================================================
#define TBM 128
#define TBN 128
#define TBK 16
#define ASTR 20
#define BSTR 136
#define NSTAGE 3
#define GEMM_SMEM ((NSTAGE*TBM*ASTR + NSTAGE*TBK*BSTR) * 4)   // 56,832 B

__device__ __forceinline__ void mma1688(float* d, const unsigned* a, const unsigned* b)
{
    asm volatile(
        "mma.sync.aligned.m16n8k8.row.col.f32.tf32.tf32.f32 "
        "{%0,%1,%2,%3},{%4,%5,%6,%7},{%8,%9},{%0,%1,%2,%3};"
        : "+f"(d[0]), "+f"(d[1]), "+f"(d[2]), "+f"(d[3])
        : "r"(a[0]), "r"(a[1]), "r"(a[2]), "r"(a[3]), "r"(b[0]), "r"(b[1]));
}

__device__ __forceinline__ void cpa16(unsigned s, const void* g)
{
    asm volatile("cp.async.ca.shared.global [%0], [%1], 16;" :: "r"(s), "l"(g));
}

__global__ __launch_bounds__(256, 2) void gemm_tf32(
    const float* __restrict__ A, const float* __restrict__ W,
    const float* __restrict__ bias, float* __restrict__ C,
    int M, int N, int K, int relu)
{
    extern __shared__ float sm[];
    float* As = sm;                             // [stage][row][k] stride ASTR
    float* Bs = sm + NSTAGE * TBM * ASTR;       // [stage][k][n]  stride BSTR

    int tid  = threadIdx.x;
    int warp = tid >> 5, lane = tid & 31;
    int wm = warp & 3, wn = warp >> 2;          // 4 x 2 warps
    int g = lane >> 2, c = lane & 3;

    int brow = blockIdx.y * TBM;
    int bcol = blockIdx.x * TBN;

    float acc[2][8][4];
    #pragma unroll
    for (int mt = 0; mt < 2; mt++)
        #pragma unroll
        for (int nt = 0; nt < 8; nt++)
            #pragma unroll
            for (int i = 0; i < 4; i++) acc[mt][nt][i] = 0.f;

    // A staging: row = tid>>1, k-off (tid&1)*8, two cpa16 per stage
    int a_row = tid >> 1, a_ko = (tid & 1) << 3;
    const float* aptr = A + (size_t)(brow + a_row) * K + a_ko;
    // B staging: k-row = tid>>4 (0..15), n-off (tid&15)*8, two cpa16 per stage
    int b_k = tid >> 4, b_n = (tid & 15) << 3;
    const float* bptr = W + (size_t)b_k * N + bcol + b_n;

    unsigned sA[NSTAGE], sB[NSTAGE];
    #pragma unroll
    for (int s = 0; s < NSTAGE; s++) {
        sA[s] = (unsigned)__cvta_generic_to_shared(&As[(s * TBM + a_row) * ASTR + a_ko]);
        sB[s] = (unsigned)__cvta_generic_to_shared(&Bs[(s * TBK + b_k) * BSTR + b_n]);
    }

    int niter = K / TBK;

    // ---- prologue: issue tiles 0 and 1 ----
    #pragma unroll
    for (int s = 0; s < 2; s++) {
        const float* ga = aptr + s * TBK;
        const float* gb = bptr + (size_t)s * TBK * N;
        cpa16(sA[s], ga);
        cpa16(sA[s] + 16, ga + 4);
        cpa16(sB[s], gb);
        cpa16(sB[s] + 16, gb + 4);
        asm volatile("cp.async.commit_group;");
    }

    int st = 0;
    for (int i = 0; i < niter; i++) {
        asm volatile("cp.async.wait_group 1;");   // stage i landed
        __syncthreads();                          // all warps done with stage (i-1)

        // ---- issue tile i+2 into stage (i+2)%3 ----
        int kt = i + 2;
        if (kt < niter) {
            int sn = kt - NSTAGE * (kt / NSTAGE);
            const float* ga = aptr + (size_t)kt * TBK;
            const float* gb = bptr + (size_t)kt * TBK * N;
            cpa16(sA[sn], ga);
            cpa16(sA[sn] + 16, ga + 4);
            cpa16(sB[sn], gb);
            cpa16(sB[sn] + 16, gb + 4);
        }
        asm volatile("cp.async.commit_group;");

        // ---- compute from stage st ----
        const float* ASP = As + st * TBM * ASTR;
        const float* BSP = Bs + st * TBK * BSTR;
        #pragma unroll
        for (int ks = 0; ks < 2; ks++) {
            int kc = ks * 8 + c;
            unsigned bf[8][2];
            #pragma unroll
            for (int nt = 0; nt < 8; nt++) {
                int n = wn * 64 + nt * 8 + g;
                bf[nt][0] = __float_as_uint(BSP[kc * BSTR + n]);
                bf[nt][1] = __float_as_uint(BSP[(kc + 4) * BSTR + n]);
            }
            #pragma unroll
            for (int mt = 0; mt < 2; mt++) {
                int r0 = wm * 32 + mt * 16 + g;
                unsigned af[4];
                af[0] = __float_as_uint(ASP[r0 * ASTR + kc]);
                af[1] = __float_as_uint(ASP[(r0 + 8) * ASTR + kc]);
                af[2] = __float_as_uint(ASP[r0 * ASTR + kc + 4]);
                af[3] = __float_as_uint(ASP[(r0 + 8) * ASTR + kc + 4]);
                #pragma unroll
                for (int nt = 0; nt < 8; nt++)
                    mma1688(acc[mt][nt], af, bf[nt]);
            }
        }

        st++;
        if (st == NSTAGE) st = 0;
    }

    // ---- epilogue: bias (+relu) + store ----
    #pragma unroll
    for (int mt = 0; mt < 2; mt++) {
        int row = brow + wm * 32 + mt * 16 + g;
        #pragma unroll
        for (int nt = 0; nt < 8; nt++) {
            int col = bcol + wn * 64 + nt * 8 + 2 * c;
            float2 bs = *(const float2*)(bias + col);
            float v0 = acc[mt][nt][0] + bs.x;
            float v1 = acc[mt][nt][1] + bs.y;
            float v2 = acc[mt][nt][2] + bs.x;
            float v3 = acc[mt][nt][3] + bs.y;
            if (relu) {
                v0 = fmaxf(v0, 0.f); v1 = fmaxf(v1, 0.f);
                v2 = fmaxf(v2, 0.f); v3 = fmaxf(v3, 0.f);
            }
            *(float2*)(C + (size_t)row * N + col)       = make_float2(v0, v1);
            *(float2*)(C + (size_t)(row + 8) * N + col) = make_float2(v2, v3);
        }
    }
}

// =====================================================================
// Attention: block per (seq m, head h, 64-row q-tile), 256 threads.
// Reads fused qkv buffer (row stride QKVN; q at +0, k at +512, v at +1024).
// =====================================================================
#define QT 64
#define KC 64
#define QSTR 129
#define KSTR 129
#define VSTR 132

__global__ __launch_bounds__(256) void attn2_kernel(
    const float* __restrict__ qkv, float* __restrict__ out,
    const int* __restrict__ lens, int Tt, int nQT)
{
    extern __shared__ float smb[];
    float* Qs  = smb;
    float* KVs = Qs + QT * QSTR;
    float* SC  = KVs + KC * VSTR;

    int tid = threadIdx.x;
    int b = blockIdx.x;
    int qt  = b % nQT; int rem = b / nQT;
    int h = rem % NHEAD; int m = rem / NHEAD;
    int q0 = qt * QT;
    int sstr = Tt + 1;

    int valid = Tt;
    if (lens) { int l = lens[m]; valid = l > 1 ? l : 1; }

    // ---- load Q tile ----
    const float* qbase = qkv + ((size_t)m * Tt + q0) * QKVN + h * DHEAD;
    for (int i = tid; i < QT * (DHEAD/4); i += 256) {
        int row = i >> 5, c4 = i & 31;
        float4 vq = *(const float4*)(qbase + (size_t)row * QKVN + 4 * c4);
        float* dst = Qs + row * QSTR + 4 * c4;
        dst[0] = vq.x; dst[1] = vq.y; dst[2] = vq.z; dst[3] = vq.w;
    }

    // ---- phase 1: raw scores ----
    int tq = (tid >> 4) << 2;
    int tk = (tid & 15) << 2;
    for (int kc = 0; kc < Tt; kc += KC) {
        __syncthreads();
        const float* kbase = qkv + ((size_t)m * Tt + kc) * QKVN + 512 + h * DHEAD;
        for (int i = tid; i < KC * (DHEAD/4); i += 256) {
            int row = i >> 5, c4 = i & 31;
            float4 vk = *(const float4*)(kbase + (size_t)row * QKVN + 4 * c4);
            float* dst = KVs + row * KSTR + 4 * c4;
            dst[0] = vk.x; dst[1] = vk.y; dst[2] = vk.z; dst[3] = vk.w;
        }
        __syncthreads();

        float acc[4][4];
        #pragma unroll
        for (int i = 0; i < 4; i++)
            #pragma unroll
            for (int j = 0; j < 4; j++) acc[i][j] = 0.f;

        const float* qp0 = Qs + (tq + 0) * QSTR;
        const float* qp1 = Qs + (tq + 1) * QSTR;
        const float* qp2 = Qs + (tq + 2) * QSTR;
        const float* qp3 = Qs + (tq + 3) * QSTR;
        const float* kp0 = KVs + (tk + 0) * KSTR;
        const float* kp1 = KVs + (tk + 1) * KSTR;
        const float* kp2 = KVs + (tk + 2) * KSTR;
        const float* kp3 = KVs + (tk + 3) * KSTR;

        #pragma unroll 4
        for (int d = 0; d < DHEAD; d++) {
            float qa[4] = { qp0[d], qp1[d], qp2[d], qp3[d] };
            float kb[4] = { kp0[d], kp1[d], kp2[d], kp3[d] };
            #pragma unroll
            for (int i = 0; i < 4; i++)
                #pragma unroll
                for (int j = 0; j < 4; j++)
                    acc[i][j] += qa[i] * kb[j];
        }
        #pragma unroll
        for (int i = 0; i < 4; i++)
            #pragma unroll
            for (int j = 0; j < 4; j++)
                SC[(tq + i) * sstr + kc + tk + j] = acc[i][j];
    }
    __syncthreads();

    // ---- phase 2: softmax per row ----
    {
        int warp = tid >> 5, lane = tid & 31;
        const float scale = 0.08838834764831845f;   // 1/sqrt(128)
        for (int rr = 0; rr < 8; rr++) {
            float* row = SC + (warp * 8 + rr) * sstr;
            float mx = -1e30f;
            for (int j = lane; j < Tt; j += 32) {
                float s = (j < valid) ? row[j] * scale : -1e9f;
                row[j] = s;
                mx = fmaxf(mx, s);
            }
            #pragma unroll
            for (int o = 16; o; o >>= 1) mx = fmaxf(mx, __shfl_xor_sync(0xffffffffu, mx, o));
            float sum = 0.f;
            for (int j = lane; j < Tt; j += 32) {
                float e = __expf(row[j] - mx);
                row[j] = e;
                sum += e;
            }
            #pragma unroll
            for (int o = 16; o; o >>= 1) sum += __shfl_xor_sync(0xffffffffu, sum, o);
            float inv = 1.f / sum;
            for (int j = lane; j < Tt; j += 32) row[j] *= inv;
        }
    }

    // ---- phase 3: P @ V ----
    int tqg = (tid >> 4) << 2;
    int td  = (tid & 15) << 3;
    float cacc[4][8];
    #pragma unroll
    for (int i = 0; i < 4; i++)
        #pragma unroll
        for (int j = 0; j < 8; j++) cacc[i][j] = 0.f;

    for (int kc = 0; kc < Tt; kc += KC) {
        __syncthreads();
        const float* vbase = qkv + ((size_t)m * Tt + kc) * QKVN + 1024 + h * DHEAD;
        for (int i = tid; i < KC * (DHEAD/4); i += 256) {
            int row = i >> 5, c4 = i & 31;
            float4 vv = *(const float4*)(vbase + (size_t)row * QKVN + 4 * c4);
            *(float4*)(KVs + row * VSTR + 4 * c4) = vv;
        }
        __syncthreads();

        const float* pp0 = SC + (tqg + 0) * sstr + kc;
        const float* pp1 = SC + (tqg + 1) * sstr + kc;
        const float* pp2 = SC + (tqg + 2) * sstr + kc;
        const float* pp3 = SC + (tqg + 3) * sstr + kc;
        #pragma unroll 2
        for (int kk = 0; kk < KC; kk++) {
            float p[4] = { pp0[kk], pp1[kk], pp2[kk], pp3[kk] };
            float4 v0 = *(const float4*)(KVs + kk * VSTR + td);
            float4 v1 = *(const float4*)(KVs + kk * VSTR + td + 4);
            float vv[8] = { v0.x, v0.y, v0.z, v0.w, v1.x, v1.y, v1.z, v1.w };
            #pragma unroll
            for (int i = 0; i < 4; i++)
                #pragma unroll
                for (int j = 0; j < 8; j++)
                    cacc[i][j] += p[i] * vv[j];
        }
    }

    // ---- store ctx (t1, stride DMODEL) ----
    float* obase = out + ((size_t)m * Tt + q0) * DMODEL + h * DHEAD;
    #pragma unroll
    for (int i = 0; i < 4; i++) {
        float* orow = obase + (size_t)(tqg + i) * DMODEL + td;
        *(float4*)(orow)     = make_float4(cacc[i][0], cacc[i][1], cacc[i][2], cacc[i][3]);
        *(float4*)(orow + 4) = make_float4(cacc[i][4], cacc[i][5], cacc[i][6], cacc[i][7]);
    }
}

// ---------------- residual add + LayerNorm, block per token -----------------
__global__ void add_ln_kernel(const float* __restrict__ x, const float* __restrict__ y,
                              const float* __restrict__ g, const float* __restrict__ b,
                              float* __restrict__ out)
{
    int t = blockIdx.x, tid = threadIdx.x;
    const float* xr = x + (size_t)t * DMODEL;
    const float* yr = y + (size_t)t * DMODEL;
    int lane = tid & 31, warp = tid >> 5;
    __shared__ float red[4];

    float h[4];
    float s = 0.f;
    #pragma unroll
    for (int i = 0; i < 4; i++) { int d = tid + i * 128; h[i] = xr[d] + yr[d]; s += h[i]; }
    #pragma unroll
    for (int o = 16; o; o >>= 1) s += __shfl_xor_sync(0xffffffffu, s, o);
    if (lane == 0) red[warp] = s;
    __syncthreads();
    s = red[0] + red[1] + red[2] + red[3];
    float mu = s * (1.f / DMODEL);

    float vs = 0.f;
    #pragma unroll
    for (int i = 0; i < 4; i++) { float dl = h[i] - mu; vs += dl * dl; }
    #pragma unroll
    for (int o = 16; o; o >>= 1) vs += __shfl_xor_sync(0xffffffffu, vs, o);
    __syncthreads();
    if (lane == 0) red[warp] = vs;
    __syncthreads();
    vs = (red[0] + red[1] + red[2] + red[3]) * (1.f / DMODEL);
    float invstd = rsqrtf(vs + 1e-5f);

    float* orow = out + (size_t)t * DMODEL;
    #pragma unroll
    for (int i = 0; i < 4; i++) {
        int d = tid + i * 128;
        orow[d] = (h[i] - mu) * invstd * g[d] + b[d];
    }
}

// ---------------- embedding + positional encoding ---------------------------
__device__ __forceinline__ float pe_val(int pos, int d)
{
    int i2 = d & ~1;
    float div = expf((float)i2 * (-9.210340371976184f / (float)DMODEL));
    float ang = (float)pos * div;
    return (d & 1) ? cosf(ang) : sinf(ang);
}

__global__ void embed_kernel(const int* __restrict__ ids, const float* __restrict__ emb,
                             float* __restrict__ x, int seqlen)
{
    int tok = blockIdx.x;
    int pos = tok % seqlen;
    int id = ids[tok];
    const float* erow = emb + (size_t)id * DMODEL;
    float* xrow = x + (size_t)tok * DMODEL;
    for (int d = threadIdx.x; d < DMODEL; d += 128)
        xrow[d] = erow[d] + pe_val(pos, d);
}

// ---------------- small epilogue kernels -------------------------------------
__global__ void copy_hidden_kernel(const float* __restrict__ x, float* __restrict__ hid)
{
    int b = blockIdx.x;
    const float* src = x + ((size_t)(b * SLEN + SLEN - 1)) * DMODEL;
    for (int d = threadIdx.x; d < DMODEL; d += 128)
        hid[b * DMODEL + d] = src[d];
}

__global__ void gather_add_kernel(const float* __restrict__ hx, const int* __restrict__ lens,
                                  float* __restrict__ sep)
{
    int r = blockIdx.x;
    int len = lens[r];
    if (len <= 0) return;
    const float* src = hx + ((size_t)(r * TLEN + len - 1)) * DMODEL;
    for (int d = threadIdx.x; d < DMODEL; d += 128)
        sep[(size_t)r * DMODEL + d] += src[d];
}

__global__ void final_kernel(const float* __restrict__ sep, const float* __restrict__ hidden,
                             const int* __restrict__ normalize, float* __restrict__ out)
{
    int r = blockIdx.x;
    int b = r / NSEP;
    int tid = threadIdx.x;
    int lane = tid & 31, warp = tid >> 5;
    int norm = *normalize;

    __shared__ float sbuf[DMODEL];
    __shared__ float red[4];

    for (int d = tid; d < DMODEL; d += 128) {
        float v = sep[(size_t)r * DMODEL + d];
        if (norm) v = fmaxf(v, 0.f);
        sbuf[d] = v;
    }
    __syncthreads();

    float scale = 1.f;
    if (norm) {
        float ss = 0.f;
        for (int d = tid; d < DMODEL; d += 128) ss += sbuf[d] * sbuf[d];
        #pragma unroll
        for (int o = 16; o; o >>= 1) ss += __shfl_xor_sync(0xffffffffu, ss, o);
        if (lane == 0) red[warp] = ss;
        __syncthreads();
        ss = red[0] + red[1] + red[2] + red[3];
        float nrm = sqrtf(ss);
        scale = 1.f / fmaxf(nrm, 1e-12f);
        __syncthreads();
    }

    float dp = 0.f;
    for (int d = tid; d < DMODEL; d += 128)
        dp += sbuf[d] * scale * hidden[(size_t)b * DMODEL + d];
    #pragma unroll
    for (int o = 16; o; o >>= 1) dp += __shfl_xor_sync(0xffffffffu, dp, o);
    if (lane == 0) red[warp] = dp;
    __syncthreads();
    if (tid == 0) out[r] = red[0] + red[1] + red[2] + red[3];
}

// ---------------- host side ---------------------------------------------------
static void gemm(const float* A, const float* Wr, const float* bias, float* C,
                 int M, int N, int K, int relu)
{
    dim3 grid(N / TBN, M / TBM);
    gemm_tf32<<<grid, 256, GEMM_SMEM>>>(A, Wr, bias, C, M, N, K, relu);
}

struct EncParams {
    const float *wr, *bqkv;
    const float *bo, *b1, *b2;
    const float *ln1g, *ln1b, *ln2g, *ln2b;
};

static void launch_attn(const float* qkv, float* out, const int* lens, int M, int Tt)
{
    int nQT = Tt / QT;
    int grid = M * NHEAD * nQT;
    size_t smem = (size_t)(QT * QSTR + KC * VSTR + QT * (Tt + 1)) * sizeof(float);
    attn2_kernel<<<grid, 256, smem>>>(qkv, out, lens, Tt, nQT);
}

static void run_encoder(float* x, float* qkv, float* t1, float* t2,
                        const EncParams& p, const int* lens, int M, int Tt)
{
    int ntok = M * Tt;
    const int LW = DMODEL * DMODEL;
    for (int l = 0; l < NLAYER; l++) {
        const float* wqkv = p.wr + (size_t)l * DMODEL * QKVN;
        const float* wo = p.wr + WQKV_SZ + 0*WTSZ + (size_t)l * LW;
        const float* w1 = p.wr + WQKV_SZ + 1*WTSZ + (size_t)l * LW;
        const float* w2 = p.wr + WQKV_SZ + 2*WTSZ + (size_t)l * LW;

        gemm(x, wqkv, p.bqkv + l * QKVN, qkv, ntok, QKVN, DMODEL, 0);

        launch_attn(qkv, t1, lens, M, Tt);

        gemm(t1, wo, p.bo + l * DMODEL, t2, ntok, DMODEL, DMODEL, 0);
        add_ln_kernel<<<ntok, 128>>>(x, t2, p.ln1g + l * DMODEL, p.ln1b + l * DMODEL, x);

        gemm(x, w1, p.b1 + l * FFDIM, t1, ntok, FFDIM, DMODEL, 1);
        gemm(t1, w2, p.b2 + l * DMODEL, t2, ntok, DMODEL, FFDIM, 0);
        add_ln_kernel<<<ntok, 128>>>(x, t2, p.ln2g + l * DMODEL, p.ln2b + l * DMODEL, x);
    }
}

extern "C" void kernel_launch(void* const* d_in, const int* in_sizes, int n_in,
                              void* d_out, int out_size)
{
    const int*   segment    = (const int*)  d_in[0];
    const int*   prev_hist  = (const int*)  d_in[1];
    const int*   hist_len   = (const int*)  d_in[2];
    const float* sep_img    = (const float*)d_in[3];
    const int*   normalize  = (const int*)  d_in[4];
    const float* embedding  = (const float*)d_in[5];

    const float* Wq   = (const float*)d_in[6];  const float* bq   = (const float*)d_in[7];
    const float* Wk   = (const float*)d_in[8];  const float* bk   = (const float*)d_in[9];
    const float* Wv   = (const float*)d_in[10]; const float* bv   = (const float*)d_in[11];
    const float* Wo   = (const float*)d_in[12]; const float* bo   = (const float*)d_in[13];
    const float* ln1g = (const float*)d_in[14]; const float* ln1b = (const float*)d_in[15];
    const float* W1   = (const float*)d_in[16]; const float* b1   = (const float*)d_in[17];
    const float* W2   = (const float*)d_in[18]; const float* b2   = (const float*)d_in[19];
    const float* ln2g = (const float*)d_in[20]; const float* ln2b = (const float*)d_in[21];
    const float* Wsep = (const float*)d_in[22];
    const float* bsep = (const float*)d_in[23];

    float *x, *qkv, *t1, *t2, *hid, *sep, *wr, *bqkv;
    cudaGetSymbolAddress((void**)&x,    g_x);
    cudaGetSymbolAddress((void**)&qkv,  g_qkv);
    cudaGetSymbolAddress((void**)&t1,   g_t1);
    cudaGetSymbolAddress((void**)&t2,   g_t2);
    cudaGetSymbolAddress((void**)&hid,  g_hidden);
    cudaGetSymbolAddress((void**)&sep,  g_sep);
    cudaGetSymbolAddress((void**)&wr,   g_wr);
    cudaGetSymbolAddress((void**)&bqkv, g_bqkv);

    cudaFuncSetAttribute(attn2_kernel, cudaFuncAttributeMaxDynamicSharedMemorySize, 140 * 1024);
    cudaFuncSetAttribute(gemm_tf32, cudaFuncAttributeMaxDynamicSharedMemorySize, GEMM_SMEM);

    // ---- launches 1-3: pack + round weights, pack biases ----
    pack_qkv<<<(WQKV_SZ / 4 + 255) / 256, 256>>>(Wq, Wk, Wv, wr);
    {
        dim3 grid(WTSZ / 4 / 256, 4);
        wround4<<<grid, 256>>>(Wo, W1, W2, Wsep, wr, WTSZ / 4);
    }
    pack_bias<<<(NLAYER * QKVN + 255) / 256, 256>>>(bq, bk, bv, bqkv);

    EncParams p;
    p.wr = wr; p.bqkv = bqkv;
    p.bo = bo; p.b1 = b1; p.b2 = b2;
    p.ln1g = ln1g; p.ln1b = ln1b; p.ln2g = ln2g; p.ln2b = ln2b;

    // ---- launch 4: main embed; launch 5: image projection ----
    embed_kernel<<<MAIN_TOK, 128>>>(segment, embedding, x, SLEN);
    gemm(sep_img, wr + WQKV_SZ + 3*WTSZ, bsep, sep, HIST_SEQ, FFDIM, IMGDIM, 0);
    // launch 6: fused QKV gemm, layer 0 main encoder (ncu -s 5 captures this)

    // ---- main encoder ----
    run_encoder(x, qkv, t1, t2, p, nullptr, BATCH, SLEN);
    copy_hidden_kernel<<<BATCH, 128>>>(x, hid);

    // ---- history encoder ----
    embed_kernel<<<HIST_TOK, 128>>>(prev_hist, embedding, x, TLEN);
    run_encoder(x, qkv, t1, t2, p, hist_len, HIST_SEQ, TLEN);

    // ---- gather last hidden, add to sep, normalize + dot ----
    gather_add_kernel<<<HIST_SEQ, 128>>>(x, hist_len, sep);
    final_kernel<<<HIST_SEQ, 128>>>(sep, hid, normalize, (float*)d_out);
}

// round 14
// speedup vs baseline: 1.7116x; 1.2215x over previous
#include <cuda_runtime.h>
#include <math.h>

// Problem constants
#define BATCH 64
#define NSEP  6
#define SLEN  256
#define TLEN  64
#define DMODEL 512
#define NHEAD 4
#define DHEAD 128
#define FFDIM 512
#define NLAYER 4
#define IMGDIM 2048
#define QKVN  1536     // fused q|k|v output width

#define MAIN_TOK (BATCH*SLEN)          // 16384
#define HIST_SEQ (BATCH*NSEP)          // 384
#define HIST_TOK (HIST_SEQ*TLEN)       // 24576
#define MAXTOK   HIST_TOK

// ---------------- scratch (device globals; no allocation allowed) ------------
__device__ float g_x  [MAXTOK*DMODEL];
__device__ float g_qkv[MAXTOK*QKVN];
__device__ float g_t1 [MAXTOK*DMODEL];
__device__ float g_t2 [MAXTOK*DMODEL];
__device__ float g_hidden[BATCH*DMODEL];
__device__ float g_sep[HIST_SEQ*DMODEL];
__device__ int   g_map[HIST_TOK];
__device__ int   g_off[HIST_SEQ + 1];
__device__ int   g_total[1];

// Pre-rounded (tf32/rna) weights:
//   [0, 3145728)  wqkv: [L][512][1536]
//   then Wo, W1, W2, Wsep (1M floats each)
#define WQKV_SZ (NLAYER*DMODEL*QKVN)
#define WTSZ    1048576
#define WR_TOTAL (WQKV_SZ + 4*WTSZ)
__device__ float g_wr[WR_TOTAL];
__device__ float g_bqkv[NLAYER*QKVN];

__device__ __forceinline__ float tf32r(float x)
{
    unsigned u;
    asm("cvt.rna.tf32.f32 %0, %1;" : "=r"(u) : "f"(x));
    return __uint_as_float(u);
}

// ---------------- weight pack+round kernels ----------------------------------
__global__ void pack_qkv(const float* __restrict__ Wq, const float* __restrict__ Wk,
                         const float* __restrict__ Wv, float* __restrict__ out)
{
    int i4 = blockIdx.x * 256 + threadIdx.x;
    int total4 = WQKV_SZ / 4;
    if (i4 >= total4) return;
    int idx = i4 * 4;
    int n = idx % QKVN;
    int lk = idx / QKVN;
    const float* src;
    int c = n;
    if (n < 512)       { src = Wq; }
    else if (n < 1024) { src = Wk; c = n - 512; }
    else               { src = Wv; c = n - 1024; }
    float4 v = *(const float4*)(src + (size_t)lk * DMODEL + c);
    v.x = tf32r(v.x); v.y = tf32r(v.y); v.z = tf32r(v.z); v.w = tf32r(v.w);
    *(float4*)(out + idx) = v;
}

__global__ void wround4(const float* w0, const float* w1, const float* w2,
                        const float* w3, float* out, int n4)
{
    const float* srcs[4] = { w0, w1, w2, w3 };
    int t = blockIdx.y;
    const float* w = srcs[t];
    float* o = out + WQKV_SZ + (size_t)t * WTSZ;
    int i = blockIdx.x * 256 + threadIdx.x;
    if (i >= n4) return;
    float4 v = ((const float4*)w)[i];
    v.x = tf32r(v.x); v.y = tf32r(v.y); v.z = tf32r(v.z); v.w = tf32r(v.w);
    ((float4*)o)[i] = v;
}

__global__ void pack_bias(const float* __restrict__ bq, const float* __restrict__ bk,
                          const float* __restrict__ bv, float* __restrict__ out)
{
    int idx = blockIdx.x * 256 + threadIdx.x;
    if (idx >= NLAYER * QKVN) return;
    int n = idx % QKVN, l = idx / QKVN;
    float v;
    if (n < 512)       v = bq[l * DMODEL + n];
    else if (n < 1024) v = bk[l * DMODEL + n - 512];
    else               v = bv[l * DMODEL + n - 1024];
    out[idx] = v;
}

// ---------------- history compaction planning --------------------------------
__global__ void plan_kernel(const int* __restrict__ lens, int* __restrict__ off,
                            int* __restrict__ total)
{
    __shared__ int s[HIST_SEQ];
    int tid = threadIdx.x;
    if (tid < HIST_SEQ) {
        int l = lens[tid];
        s[tid] = (l > 0) ? l : 0;
    }
    __syncthreads();
    if (tid == 0) {
        int acc = 0;
        for (int r = 0; r < HIST_SEQ; r++) { off[r] = acc; acc += s[r]; }
        off[HIST_SEQ] = acc;
        total[0] = acc;
    }
}

__global__ void fill_map(const int* __restrict__ lens, const int* __restrict__ off,
                         int* __restrict__ map)
{
    int t = blockIdx.x * 256 + threadIdx.x;
    if (t >= HIST_TOK) return;
    int r = t / TLEN, p = t % TLEN;
    int l = lens[r];
    int eff = (l > 0) ? l : 0;
    if (p < eff) map[off[r] + p] = t;
}

// =====================================================================
// tf32 tensor-core GEMM (R13 pipeline) + optional device-side M limit.
// =====================================================================
#define TBM 128
#define TBN 128
#define TBK 16
#define ASTR 20
#define BSTR 136
#define NSTAGE 3
#define GEMM_SMEM ((NSTAGE*TBM*ASTR + NSTAGE*TBK*BSTR) * 4)

__device__ __forceinline__ void mma1688(float* d, const unsigned* a, const unsigned* b)
{
    asm volatile(
        "mma.sync.aligned.m16n8k8.row.col.f32.tf32.tf32.f32 "
        "{%0,%1,%2,%3},{%4,%5,%6,%7},{%8,%9},{%0,%1,%2,%3};"
        : "+f"(d[0]), "+f"(d[1]), "+f"(d[2]), "+f"(d[3])
        : "r"(a[0]), "r"(a[1]), "r"(a[2]), "r"(a[3]), "r"(b[0]), "r"(b[1]));
}

__device__ __forceinline__ void cpa16(unsigned s, const void* g)
{
    asm volatile("cp.async.ca.shared.global [%0], [%1], 16;" :: "r"(s), "l"(g));
}

__global__ __launch_bounds__(256, 2) void gemm_tf32(
    const float* __restrict__ A, const float* __restrict__ W,
    const float* __restrict__ bias, float* __restrict__ C,
    int M, int N, int K, int relu, const int* __restrict__ mlimit)
{
    int brow = blockIdx.y * TBM;
    if (mlimit && brow >= mlimit[0]) return;   // compacted-M early exit

    extern __shared__ float sm[];
    float* As = sm;
    float* Bs = sm + NSTAGE * TBM * ASTR;

    int tid  = threadIdx.x;
    int warp = tid >> 5, lane = tid & 31;
    int wm = warp & 3, wn = warp >> 2;
    int g = lane >> 2, c = lane & 3;

    int bcol = blockIdx.x * TBN;

    float acc[2][8][4];
    #pragma unroll
    for (int mt = 0; mt < 2; mt++)
        #pragma unroll
        for (int nt = 0; nt < 8; nt++)
            #pragma unroll
            for (int i = 0; i < 4; i++) acc[mt][nt][i] = 0.f;

    int a_row = tid >> 1, a_ko = (tid & 1) << 3;
    const float* aptr = A + (size_t)(brow + a_row) * K + a_ko;
    int b_k = tid >> 4, b_n = (tid & 15) << 3;
    const float* bptr = W + (size_t)b_k * N + bcol + b_n;

    unsigned sA[NSTAGE], sB[NSTAGE];
    #pragma unroll
    for (int s = 0; s < NSTAGE; s++) {
        sA[s] = (unsigned)__cvta_generic_to_shared(&As[(s * TBM + a_row) * ASTR + a_ko]);
        sB[s] = (unsigned)__cvta_generic_to_shared(&Bs[(s * TBK + b_k) * BSTR + b_n]);
    }

    int niter = K / TBK;

    #pragma unroll
    for (int s = 0; s < 2; s++) {
        const float* ga = aptr + s * TBK;
        const float* gb = bptr + (size_t)s * TBK * N;
        cpa16(sA[s], ga);
        cpa16(sA[s] + 16, ga + 4);
        cpa16(sB[s], gb);
        cpa16(sB[s] + 16, gb + 4);
        asm volatile("cp.async.commit_group;");
    }

    int st = 0;
    for (int i = 0; i < niter; i++) {
        asm volatile("cp.async.wait_group 1;");
        __syncthreads();

        int kt = i + 2;
        if (kt < niter) {
            int sn = kt - NSTAGE * (kt / NSTAGE);
            const float* ga = aptr + (size_t)kt * TBK;
            const float* gb = bptr + (size_t)kt * TBK * N;
            cpa16(sA[sn], ga);
            cpa16(sA[sn] + 16, ga + 4);
            cpa16(sB[sn], gb);
            cpa16(sB[sn] + 16, gb + 4);
        }
        asm volatile("cp.async.commit_group;");

        const float* ASP = As + st * TBM * ASTR;
        const float* BSP = Bs + st * TBK * BSTR;
        #pragma unroll
        for (int ks = 0; ks < 2; ks++) {
            int kc = ks * 8 + c;
            unsigned bf[8][2];
            #pragma unroll
            for (int nt = 0; nt < 8; nt++) {
                int n = wn * 64 + nt * 8 + g;
                bf[nt][0] = __float_as_uint(BSP[kc * BSTR + n]);
                bf[nt][1] = __float_as_uint(BSP[(kc + 4) * BSTR + n]);
            }
            #pragma unroll
            for (int mt = 0; mt < 2; mt++) {
                int r0 = wm * 32 + mt * 16 + g;
                unsigned af[4];
                af[0] = __float_as_uint(ASP[r0 * ASTR + kc]);
                af[1] = __float_as_uint(ASP[(r0 + 8) * ASTR + kc]);
                af[2] = __float_as_uint(ASP[r0 * ASTR + kc + 4]);
                af[3] = __float_as_uint(ASP[(r0 + 8) * ASTR + kc + 4]);
                #pragma unroll
                for (int nt = 0; nt < 8; nt++)
                    mma1688(acc[mt][nt], af, bf[nt]);
            }
        }

        st++;
        if (st == NSTAGE) st = 0;
    }

    #pragma unroll
    for (int mt = 0; mt < 2; mt++) {
        int row = brow + wm * 32 + mt * 16 + g;
        #pragma unroll
        for (int nt = 0; nt < 8; nt++) {
            int col = bcol + wn * 64 + nt * 8 + 2 * c;
            float2 bs = *(const float2*)(bias + col);
            float v0 = acc[mt][nt][0] + bs.x;
            float v1 = acc[mt][nt][1] + bs.y;
            float v2 = acc[mt][nt][2] + bs.x;
            float v3 = acc[mt][nt][3] + bs.y;
            if (relu) {
                v0 = fmaxf(v0, 0.f); v1 = fmaxf(v1, 0.f);
                v2 = fmaxf(v2, 0.f); v3 = fmaxf(v3, 0.f);
            }
            *(float2*)(C + (size_t)row * N + col)       = make_float2(v0, v1);
            *(float2*)(C + (size_t)(row + 8) * N + col) = make_float2(v2, v3);
        }
    }
}

// =====================================================================
// Main attention (full sequences, Tt=256): block per (m, h, 64-q-tile).
// =====================================================================
#define QT 64
#define KC 64
#define QSTR 129
#define KSTR 129
#define VSTR 132

__global__ __launch_bounds__(256) void attn2_kernel(
    const float* __restrict__ qkv, float* __restrict__ out, int Tt, int nQT)
{
    extern __shared__ float smb[];
    float* Qs  = smb;
    float* KVs = Qs + QT * QSTR;
    float* SC  = KVs + KC * VSTR;

    int tid = threadIdx.x;
    int b = blockIdx.x;
    int qt  = b % nQT; int rem = b / nQT;
    int h = rem % NHEAD; int m = rem / NHEAD;
    int q0 = qt * QT;
    int sstr = Tt + 1;

    const float* qbase = qkv + ((size_t)m * Tt + q0) * QKVN + h * DHEAD;
    for (int i = tid; i < QT * (DHEAD/4); i += 256) {
        int row = i >> 5, c4 = i & 31;
        float4 vq = *(const float4*)(qbase + (size_t)row * QKVN + 4 * c4);
        float* dst = Qs + row * QSTR + 4 * c4;
        dst[0] = vq.x; dst[1] = vq.y; dst[2] = vq.z; dst[3] = vq.w;
    }

    int tq = (tid >> 4) << 2;
    int tk = (tid & 15) << 2;
    for (int kc = 0; kc < Tt; kc += KC) {
        __syncthreads();
        const float* kbase = qkv + ((size_t)m * Tt + kc) * QKVN + 512 + h * DHEAD;
        for (int i = tid; i < KC * (DHEAD/4); i += 256) {
            int row = i >> 5, c4 = i & 31;
            float4 vk = *(const float4*)(kbase + (size_t)row * QKVN + 4 * c4);
            float* dst = KVs + row * KSTR + 4 * c4;
            dst[0] = vk.x; dst[1] = vk.y; dst[2] = vk.z; dst[3] = vk.w;
        }
        __syncthreads();

        float acc[4][4];
        #pragma unroll
        for (int i = 0; i < 4; i++)
            #pragma unroll
            for (int j = 0; j < 4; j++) acc[i][j] = 0.f;

        const float* qp0 = Qs + (tq + 0) * QSTR;
        const float* qp1 = Qs + (tq + 1) * QSTR;
        const float* qp2 = Qs + (tq + 2) * QSTR;
        const float* qp3 = Qs + (tq + 3) * QSTR;
        const float* kp0 = KVs + (tk + 0) * KSTR;
        const float* kp1 = KVs + (tk + 1) * KSTR;
        const float* kp2 = KVs + (tk + 2) * KSTR;
        const float* kp3 = KVs + (tk + 3) * KSTR;

        #pragma unroll 4
        for (int d = 0; d < DHEAD; d++) {
            float qa[4] = { qp0[d], qp1[d], qp2[d], qp3[d] };
            float kb[4] = { kp0[d], kp1[d], kp2[d], kp3[d] };
            #pragma unroll
            for (int i = 0; i < 4; i++)
                #pragma unroll
                for (int j = 0; j < 4; j++)
                    acc[i][j] += qa[i] * kb[j];
        }
        #pragma unroll
        for (int i = 0; i < 4; i++)
            #pragma unroll
            for (int j = 0; j < 4; j++)
                SC[(tq + i) * sstr + kc + tk + j] = acc[i][j];
    }
    __syncthreads();

    {
        int warp = tid >> 5, lane = tid & 31;
        const float scale = 0.08838834764831845f;
        for (int rr = 0; rr < 8; rr++) {
            float* row = SC + (warp * 8 + rr) * sstr;
            float mx = -1e30f;
            for (int j = lane; j < Tt; j += 32) {
                float s = row[j] * scale;
                row[j] = s;
                mx = fmaxf(mx, s);
            }
            #pragma unroll
            for (int o = 16; o; o >>= 1) mx = fmaxf(mx, __shfl_xor_sync(0xffffffffu, mx, o));
            float sum = 0.f;
            for (int j = lane; j < Tt; j += 32) {
                float e = __expf(row[j] - mx);
                row[j] = e;
                sum += e;
            }
            #pragma unroll
            for (int o = 16; o; o >>= 1) sum += __shfl_xor_sync(0xffffffffu, sum, o);
            float inv = 1.f / sum;
            for (int j = lane; j < Tt; j += 32) row[j] *= inv;
        }
    }

    int tqg = (tid >> 4) << 2;
    int td  = (tid & 15) << 3;
    float cacc[4][8];
    #pragma unroll
    for (int i = 0; i < 4; i++)
        #pragma unroll
        for (int j = 0; j < 8; j++) cacc[i][j] = 0.f;

    for (int kc = 0; kc < Tt; kc += KC) {
        __syncthreads();
        const float* vbase = qkv + ((size_t)m * Tt + kc) * QKVN + 1024 + h * DHEAD;
        for (int i = tid; i < KC * (DHEAD/4); i += 256) {
            int row = i >> 5, c4 = i & 31;
            float4 vv = *(const float4*)(vbase + (size_t)row * QKVN + 4 * c4);
            *(float4*)(KVs + row * VSTR + 4 * c4) = vv;
        }
        __syncthreads();

        const float* pp0 = SC + (tqg + 0) * sstr + kc;
        const float* pp1 = SC + (tqg + 1) * sstr + kc;
        const float* pp2 = SC + (tqg + 2) * sstr + kc;
        const float* pp3 = SC + (tqg + 3) * sstr + kc;
        #pragma unroll 2
        for (int kk = 0; kk < KC; kk++) {
            float p[4] = { pp0[kk], pp1[kk], pp2[kk], pp3[kk] };
            float4 v0 = *(const float4*)(KVs + kk * VSTR + td);
            float4 v1 = *(const float4*)(KVs + kk * VSTR + td + 4);
            float vv[8] = { v0.x, v0.y, v0.z, v0.w, v1.x, v1.y, v1.z, v1.w };
            #pragma unroll
            for (int i = 0; i < 4; i++)
                #pragma unroll
                for (int j = 0; j < 8; j++)
                    cacc[i][j] += p[i] * vv[j];
        }
    }

    float* obase = out + ((size_t)m * Tt + q0) * DMODEL + h * DHEAD;
    #pragma unroll
    for (int i = 0; i < 4; i++) {
        float* orow = obase + (size_t)(tqg + i) * DMODEL + td;
        *(float4*)(orow)     = make_float4(cacc[i][0], cacc[i][1], cacc[i][2], cacc[i][3]);
        *(float4*)(orow + 4) = make_float4(cacc[i][4], cacc[i][5], cacc[i][6], cacc[i][7]);
    }
}

// =====================================================================
// History attention (compacted): block per (sequence, head), <=64 rows.
// Smem zero-padded so dead keys contribute exactly 0.
// =====================================================================
__global__ __launch_bounds__(256) void attn_hist_kernel(
    const float* __restrict__ qkv, float* __restrict__ out,
    const int* __restrict__ lens, const int* __restrict__ off)
{
    __shared__ float Qs[64 * QSTR];
    __shared__ float KVs[64 * VSTR];
    __shared__ float SC[64 * 65];

    int tid = threadIdx.x;
    int b = blockIdx.x;
    int h = b & 3, r = b >> 2;
    int eff = lens[r];
    if (eff <= 0) return;
    int base = off[r];

    // zero-fill (dead rows/keys contribute 0)
    for (int i = tid; i < 64 * QSTR; i += 256) Qs[i] = 0.f;
    for (int i = tid; i < 64 * VSTR; i += 256) KVs[i] = 0.f;
    __syncthreads();

    // load Q,K rows < eff
    for (int i = tid; i < eff * 32; i += 256) {
        int row = i >> 5, c4 = i & 31;
        float4 vq = *(const float4*)(qkv + (size_t)(base + row) * QKVN + h * DHEAD + 4 * c4);
        float* dq = Qs + row * QSTR + 4 * c4;
        dq[0] = vq.x; dq[1] = vq.y; dq[2] = vq.z; dq[3] = vq.w;
        float4 vk = *(const float4*)(qkv + (size_t)(base + row) * QKVN + 512 + h * DHEAD + 4 * c4);
        float* dk = KVs + row * VSTR + 4 * c4;
        dk[0] = vk.x; dk[1] = vk.y; dk[2] = vk.z; dk[3] = vk.w;
    }
    __syncthreads();

    // scores 64x64 (dead entries are 0; masked later)
    int tq = (tid >> 4) << 2;
    int tk = (tid & 15) << 2;
    {
        float acc[4][4];
        #pragma unroll
        for (int i = 0; i < 4; i++)
            #pragma unroll
            for (int j = 0; j < 4; j++) acc[i][j] = 0.f;

        const float* qp0 = Qs + (tq + 0) * QSTR;
        const float* qp1 = Qs + (tq + 1) * QSTR;
        const float* qp2 = Qs + (tq + 2) * QSTR;
        const float* qp3 = Qs + (tq + 3) * QSTR;
        const float* kp0 = KVs + (tk + 0) * VSTR;
        const float* kp1 = KVs + (tk + 1) * VSTR;
        const float* kp2 = KVs + (tk + 2) * VSTR;
        const float* kp3 = KVs + (tk + 3) * VSTR;

        #pragma unroll 4
        for (int d = 0; d < DHEAD; d++) {
            float qa[4] = { qp0[d], qp1[d], qp2[d], qp3[d] };
            float kb[4] = { kp0[d], kp1[d], kp2[d], kp3[d] };
            #pragma unroll
            for (int i = 0; i < 4; i++)
                #pragma unroll
                for (int j = 0; j < 4; j++)
                    acc[i][j] += qa[i] * kb[j];
        }
        #pragma unroll
        for (int i = 0; i < 4; i++)
            #pragma unroll
            for (int j = 0; j < 4; j++)
                SC[(tq + i) * 65 + tk + j] = acc[i][j];
    }
    __syncthreads();

    // softmax on live rows only, mask keys >= eff
    {
        int warp = tid >> 5, lane = tid & 31;
        const float scale = 0.08838834764831845f;
        for (int rr = 0; rr < 8; rr++) {
            int ri = warp * 8 + rr;
            if (ri >= eff) continue;
            float* row = SC + ri * 65;
            float mx = -1e30f;
            for (int j = lane; j < 64; j += 32) {
                float s = (j < eff) ? row[j] * scale : -1e9f;
                row[j] = s;
                mx = fmaxf(mx, s);
            }
            #pragma unroll
            for (int o = 16; o; o >>= 1) mx = fmaxf(mx, __shfl_xor_sync(0xffffffffu, mx, o));
            float sum = 0.f;
            for (int j = lane; j < 64; j += 32) {
                float e = __expf(row[j] - mx);
                row[j] = e;
                sum += e;
            }
            #pragma unroll
            for (int o = 16; o; o >>= 1) sum += __shfl_xor_sync(0xffffffffu, sum, o);
            float inv = 1.f / sum;
            for (int j = lane; j < 64; j += 32) row[j] *= inv;
        }
    }
    __syncthreads();

    // load V rows < eff (dead rows remain zero)
    for (int i = tid; i < eff * 32; i += 256) {
        int row = i >> 5, c4 = i & 31;
        float4 vv = *(const float4*)(qkv + (size_t)(base + row) * QKVN + 1024 + h * DHEAD + 4 * c4);
        *(float4*)(KVs + row * VSTR + 4 * c4) = vv;
    }
    __syncthreads();

    // P @ V, store live rows
    int tqg = (tid >> 4) << 2;
    int td  = (tid & 15) << 3;
    float cacc[4][8];
    #pragma unroll
    for (int i = 0; i < 4; i++)
        #pragma unroll
        for (int j = 0; j < 8; j++) cacc[i][j] = 0.f;

    const float* pp0 = SC + (tqg + 0) * 65;
    const float* pp1 = SC + (tqg + 1) * 65;
    const float* pp2 = SC + (tqg + 2) * 65;
    const float* pp3 = SC + (tqg + 3) * 65;
    #pragma unroll 2
    for (int kk = 0; kk < 64; kk++) {
        float p[4] = { pp0[kk], pp1[kk], pp2[kk], pp3[kk] };
        float4 v0 = *(const float4*)(KVs + kk * VSTR + td);
        float4 v1 = *(const float4*)(KVs + kk * VSTR + td + 4);
        float vv[8] = { v0.x, v0.y, v0.z, v0.w, v1.x, v1.y, v1.z, v1.w };
        #pragma unroll
        for (int i = 0; i < 4; i++)
            #pragma unroll
            for (int j = 0; j < 8; j++)
                cacc[i][j] += p[i] * vv[j];
    }

    #pragma unroll
    for (int i = 0; i < 4; i++) {
        int ri = tqg + i;
        if (ri >= eff) continue;
        float* orow = out + (size_t)(base + ri) * DMODEL + h * DHEAD + td;
        *(float4*)(orow)     = make_float4(cacc[i][0], cacc[i][1], cacc[i][2], cacc[i][3]);
        *(float4*)(orow + 4) = make_float4(cacc[i][4], cacc[i][5], cacc[i][6], cacc[i][7]);
    }
}

// ---------------- residual add + LayerNorm (optional device M limit) ---------
__global__ void add_ln_kernel(const float* __restrict__ x, const float* __restrict__ y,
                              const float* __restrict__ g, const float* __restrict__ b,
                              float* __restrict__ out, const int* __restrict__ mlimit)
{
    int t = blockIdx.x;
    if (mlimit && t >= mlimit[0]) return;
    int tid = threadIdx.x;
    const float* xr = x + (size_t)t * DMODEL;
    const float* yr = y + (size_t)t * DMODEL;
    int lane = tid & 31, warp = tid >> 5;
    __shared__ float red[4];

    float h[4];
    float s = 0.f;
    #pragma unroll
    for (int i = 0; i < 4; i++) { int d = tid + i * 128; h[i] = xr[d] + yr[d]; s += h[i]; }
    #pragma unroll
    for (int o = 16; o; o >>= 1) s += __shfl_xor_sync(0xffffffffu, s, o);
    if (lane == 0) red[warp] = s;
    __syncthreads();
    s = red[0] + red[1] + red[2] + red[3];
    float mu = s * (1.f / DMODEL);

    float vs = 0.f;
    #pragma unroll
    for (int i = 0; i < 4; i++) { float dl = h[i] - mu; vs += dl * dl; }
    #pragma unroll
    for (int o = 16; o; o >>= 1) vs += __shfl_xor_sync(0xffffffffu, vs, o);
    __syncthreads();
    if (lane == 0) red[warp] = vs;
    __syncthreads();
    vs = (red[0] + red[1] + red[2] + red[3]) * (1.f / DMODEL);
    float invstd = rsqrtf(vs + 1e-5f);

    float* orow = out + (size_t)t * DMODEL;
    #pragma unroll
    for (int i = 0; i < 4; i++) {
        int d = tid + i * 128;
        orow[d] = (h[i] - mu) * invstd * g[d] + b[d];
    }
}

// ---------------- embedding + positional encoding ---------------------------
__device__ __forceinline__ float pe_val(int pos, int d)
{
    int i2 = d & ~1;
    float div = expf((float)i2 * (-9.210340371976184f / (float)DMODEL));
    float ang = (float)pos * div;
    return (d & 1) ? cosf(ang) : sinf(ang);
}

__global__ void embed_kernel(const int* __restrict__ ids, const float* __restrict__ emb,
                             float* __restrict__ x, int seqlen)
{
    int tok = blockIdx.x;
    int pos = tok % seqlen;
    int id = ids[tok];
    const float* erow = emb + (size_t)id * DMODEL;
    float* xrow = x + (size_t)tok * DMODEL;
    for (int d = threadIdx.x; d < DMODEL; d += 128)
        xrow[d] = erow[d] + pe_val(pos, d);
}

__global__ void embed_hist_kernel(const int* __restrict__ ids, const float* __restrict__ emb,
                                  float* __restrict__ x, const int* __restrict__ map,
                                  const int* __restrict__ total)
{
    int b = blockIdx.x;
    if (b >= total[0]) return;
    int t = map[b];
    int pos = t % TLEN;
    int id = ids[t];
    const float* erow = emb + (size_t)id * DMODEL;
    float* xrow = x + (size_t)b * DMODEL;
    for (int d = threadIdx.x; d < DMODEL; d += 128)
        xrow[d] = erow[d] + pe_val(pos, d);
}

// ---------------- small epilogue kernels -------------------------------------
__global__ void copy_hidden_kernel(const float* __restrict__ x, float* __restrict__ hid)
{
    int b = blockIdx.x;
    const float* src = x + ((size_t)(b * SLEN + SLEN - 1)) * DMODEL;
    for (int d = threadIdx.x; d < DMODEL; d += 128)
        hid[b * DMODEL + d] = src[d];
}

__global__ void gather_add_kernel(const float* __restrict__ hx, const int* __restrict__ lens,
                                  const int* __restrict__ off, float* __restrict__ sep)
{
    int r = blockIdx.x;
    int len = lens[r];
    if (len <= 0) return;
    const float* src = hx + (size_t)(off[r] + len - 1) * DMODEL;
    for (int d = threadIdx.x; d < DMODEL; d += 128)
        sep[(size_t)r * DMODEL + d] += src[d];
}

__global__ void final_kernel(const float* __restrict__ sep, const float* __restrict__ hidden,
                             const int* __restrict__ normalize, float* __restrict__ out)
{
    int r = blockIdx.x;
    int b = r / NSEP;
    int tid = threadIdx.x;
    int lane = tid & 31, warp = tid >> 5;
    int norm = *normalize;

    __shared__ float sbuf[DMODEL];
    __shared__ float red[4];

    for (int d = tid; d < DMODEL; d += 128) {
        float v = sep[(size_t)r * DMODEL + d];
        if (norm) v = fmaxf(v, 0.f);
        sbuf[d] = v;
    }
    __syncthreads();

    float scale = 1.f;
    if (norm) {
        float ss = 0.f;
        for (int d = tid; d < DMODEL; d += 128) ss += sbuf[d] * sbuf[d];
        #pragma unroll
        for (int o = 16; o; o >>= 1) ss += __shfl_xor_sync(0xffffffffu, ss, o);
        if (lane == 0) red[warp] = ss;
        __syncthreads();
        ss = red[0] + red[1] + red[2] + red[3];
        float nrm = sqrtf(ss);
        scale = 1.f / fmaxf(nrm, 1e-12f);
        __syncthreads();
    }

    float dp = 0.f;
    for (int d = tid; d < DMODEL; d += 128)
        dp += sbuf[d] * scale * hidden[(size_t)b * DMODEL + d];
    #pragma unroll
    for (int o = 16; o; o >>= 1) dp += __shfl_xor_sync(0xffffffffu, dp, o);
    if (lane == 0) red[warp] = dp;
    __syncthreads();
    if (tid == 0) out[r] = red[0] + red[1] + red[2] + red[3];
}

// ---------------- host side ---------------------------------------------------
static void gemm(const float* A, const float* Wr, const float* bias, float* C,
                 int M, int N, int K, int relu, const int* mlimit)
{
    dim3 grid(N / TBN, M / TBM);
    gemm_tf32<<<grid, 256, GEMM_SMEM>>>(A, Wr, bias, C, M, N, K, relu, mlimit);
}

struct EncParams {
    const float *wr, *bqkv;
    const float *bo, *b1, *b2;
    const float *ln1g, *ln1b, *ln2g, *ln2b;
};

static void run_encoder_main(float* x, float* qkv, float* t1, float* t2, const EncParams& p)
{
    int ntok = MAIN_TOK;
    const int LW = DMODEL * DMODEL;
    size_t asmem = (size_t)(QT * QSTR + KC * VSTR + QT * (SLEN + 1)) * sizeof(float);
    for (int l = 0; l < NLAYER; l++) {
        const float* wqkv = p.wr + (size_t)l * DMODEL * QKVN;
        const float* wo = p.wr + WQKV_SZ + 0*WTSZ + (size_t)l * LW;
        const float* w1 = p.wr + WQKV_SZ + 1*WTSZ + (size_t)l * LW;
        const float* w2 = p.wr + WQKV_SZ + 2*WTSZ + (size_t)l * LW;

        gemm(x, wqkv, p.bqkv + l * QKVN, qkv, ntok, QKVN, DMODEL, 0, nullptr);
        attn2_kernel<<<BATCH * NHEAD * (SLEN / QT), 256, asmem>>>(qkv, t1, SLEN, SLEN / QT);
        gemm(t1, wo, p.bo + l * DMODEL, t2, ntok, DMODEL, DMODEL, 0, nullptr);
        add_ln_kernel<<<ntok, 128>>>(x, t2, p.ln1g + l * DMODEL, p.ln1b + l * DMODEL, x, nullptr);
        gemm(x, w1, p.b1 + l * FFDIM, t1, ntok, FFDIM, DMODEL, 1, nullptr);
        gemm(t1, w2, p.b2 + l * DMODEL, t2, ntok, DMODEL, FFDIM, 0, nullptr);
        add_ln_kernel<<<ntok, 128>>>(x, t2, p.ln2g + l * DMODEL, p.ln2b + l * DMODEL, x, nullptr);
    }
}

static void run_encoder_hist(float* x, float* qkv, float* t1, float* t2, const EncParams& p,
                             const int* lens, const int* off, const int* total)
{
    int ntok = HIST_TOK;    // fixed grids; blocks early-exit past *total
    const int LW = DMODEL * DMODEL;
    for (int l = 0; l < NLAYER; l++) {
        const float* wqkv = p.wr + (size_t)l * DMODEL * QKVN;
        const float* wo = p.wr + WQKV_SZ + 0*WTSZ + (size_t)l * LW;
        const float* w1 = p.wr + WQKV_SZ + 1*WTSZ + (size_t)l * LW;
        const float* w2 = p.wr + WQKV_SZ + 2*WTSZ + (size_t)l * LW;

        gemm(x, wqkv, p.bqkv + l * QKVN, qkv, ntok, QKVN, DMODEL, 0, total);
        attn_hist_kernel<<<HIST_SEQ * NHEAD, 256>>>(qkv, t1, lens, off);
        gemm(t1, wo, p.bo + l * DMODEL, t2, ntok, DMODEL, DMODEL, 0, total);
        add_ln_kernel<<<ntok, 128>>>(x, t2, p.ln1g + l * DMODEL, p.ln1b + l * DMODEL, x, total);
        gemm(x, w1, p.b1 + l * FFDIM, t1, ntok, FFDIM, DMODEL, 1, total);
        gemm(t1, w2, p.b2 + l * DMODEL, t2, ntok, DMODEL, FFDIM, 0, total);
        add_ln_kernel<<<ntok, 128>>>(x, t2, p.ln2g + l * DMODEL, p.ln2b + l * DMODEL, x, total);
    }
}

extern "C" void kernel_launch(void* const* d_in, const int* in_sizes, int n_in,
                              void* d_out, int out_size)
{
    const int*   segment    = (const int*)  d_in[0];
    const int*   prev_hist  = (const int*)  d_in[1];
    const int*   hist_len   = (const int*)  d_in[2];
    const float* sep_img    = (const float*)d_in[3];
    const int*   normalize  = (const int*)  d_in[4];
    const float* embedding  = (const float*)d_in[5];

    const float* Wq   = (const float*)d_in[6];  const float* bq   = (const float*)d_in[7];
    const float* Wk   = (const float*)d_in[8];  const float* bk   = (const float*)d_in[9];
    const float* Wv   = (const float*)d_in[10]; const float* bv   = (const float*)d_in[11];
    const float* Wo   = (const float*)d_in[12]; const float* bo   = (const float*)d_in[13];
    const float* ln1g = (const float*)d_in[14]; const float* ln1b = (const float*)d_in[15];
    const float* W1   = (const float*)d_in[16]; const float* b1   = (const float*)d_in[17];
    const float* W2   = (const float*)d_in[18]; const float* b2   = (const float*)d_in[19];
    const float* ln2g = (const float*)d_in[20]; const float* ln2b = (const float*)d_in[21];
    const float* Wsep = (const float*)d_in[22];
    const float* bsep = (const float*)d_in[23];

    float *x, *qkv, *t1, *t2, *hid, *sep, *wr, *bqkv;
    int *map, *off, *total;
    cudaGetSymbolAddress((void**)&x,     g_x);
    cudaGetSymbolAddress((void**)&qkv,   g_qkv);
    cudaGetSymbolAddress((void**)&t1,    g_t1);
    cudaGetSymbolAddress((void**)&t2,    g_t2);
    cudaGetSymbolAddress((void**)&hid,   g_hidden);
    cudaGetSymbolAddress((void**)&sep,   g_sep);
    cudaGetSymbolAddress((void**)&wr,    g_wr);
    cudaGetSymbolAddress((void**)&bqkv,  g_bqkv);
    cudaGetSymbolAddress((void**)&map,   g_map);
    cudaGetSymbolAddress((void**)&off,   g_off);
    cudaGetSymbolAddress((void**)&total, g_total);

    cudaFuncSetAttribute(attn2_kernel, cudaFuncAttributeMaxDynamicSharedMemorySize, 140 * 1024);
    cudaFuncSetAttribute(gemm_tf32, cudaFuncAttributeMaxDynamicSharedMemorySize, GEMM_SMEM);

    // ---- weight pack + history plan ----
    pack_qkv<<<(WQKV_SZ / 4 + 255) / 256, 256>>>(Wq, Wk, Wv, wr);
    {
        dim3 grid(WTSZ / 4 / 256, 4);
        wround4<<<grid, 256>>>(Wo, W1, W2, Wsep, wr, WTSZ / 4);
    }
    pack_bias<<<(NLAYER * QKVN + 255) / 256, 256>>>(bq, bk, bv, bqkv);
    plan_kernel<<<1, 512>>>(hist_len, off, total);
    fill_map<<<(HIST_TOK + 255) / 256, 256>>>(hist_len, off, map);

    EncParams p;
    p.wr = wr; p.bqkv = bqkv;
    p.bo = bo; p.b1 = b1; p.b2 = b2;
    p.ln1g = ln1g; p.ln1b = ln1b; p.ln2g = ln2g; p.ln2b = ln2b;

    // ---- main encoder ----
    embed_kernel<<<MAIN_TOK, 128>>>(segment, embedding, x, SLEN);
    gemm(sep_img, wr + WQKV_SZ + 3*WTSZ, bsep, sep, HIST_SEQ, FFDIM, IMGDIM, 0, nullptr);
    run_encoder_main(x, qkv, t1, t2, p);
    copy_hidden_kernel<<<BATCH, 128>>>(x, hid);

    // ---- history encoder (compacted) ----
    embed_hist_kernel<<<HIST_TOK, 128>>>(prev_hist, embedding, x, map, total);
    run_encoder_hist(x, qkv, t1, t2, p, hist_len, off, total);

    // ---- gather last hidden, add to sep, normalize + dot ----
    gather_add_kernel<<<HIST_SEQ, 128>>>(x, hist_len, off, sep);
    final_kernel<<<HIST_SEQ, 128>>>(sep, hid, normalize, (float*)d_out);
}